// round 15
// baseline (speedup 1.0000x reference)
#include <cuda_runtime.h>
#include <cuda_bf16.h>
#include <stdint.h>

// ============================================================================
// Problem constants
// ============================================================================
#define BA 8192
#define BB 16384
#define DIM 1024
#define LOSS_SCALE 20.0f
#define LOG2E 1.4426950408889634f
#define M_FIX 21.0f                    // global logit bound (|logit| <= ~20.2)
#define M2 (M_FIX * LOG2E)             // fixed max in log2 domain

#define TM 128            // item rows
#define TN 256            // item cols
#define TKS 128           // K bytes per pipeline stage
#define STAGES 2
#define KSTAGES (DIM / TKS)           // 8 stages per item
#define NCHUNK (BB / TN)              // 64 column chunks
#define ROWBLOCKS (BA / TM)           // 64
#define NITEMS (ROWBLOCKS * NCHUNK)   // 4096 work items
#define THREADS 256

// ============================================================================
// Device scratch
// ============================================================================
__device__ __align__(128) int8_t g_a_q[(size_t)BA * DIM];   // 8 MB
__device__ __align__(128) int8_t g_b_q[(size_t)BB * DIM];   // 16 MB
__device__ float g_saL[BA];    // 20 * log2e * per-row dequant scale for A
__device__ float g_sb[BB];     // per-row dequant scale for B
__device__ float g_pos[BA];
__device__ float g_ps[NCHUNK * BA];   // transposed: [chunk][row] partial sums
__device__ float g_part[ROWBLOCKS];
__device__ unsigned int g_ctr;

// ============================================================================
// SMEM layout. int8 rows: 128 data bytes + 16 pad = 144 B pitch.
// ============================================================================
#define PITCH_B 144
#define A_STAGE_BYTES (128 * PITCH_B)        // 18432
#define B_STAGE_BYTES (256 * PITCH_B)        // 36864
#define SM_A(stg) ((stg) * A_STAGE_BYTES)
#define SM_B(stg) (STAGES * A_STAGE_BYTES + (stg) * B_STAGE_BYTES)
#define SM_RED (STAGES * (A_STAGE_BYTES + B_STAGE_BYTES))  // float red[4][128]
#define SMEM_TOTAL (SM_RED + 4 * 128 * 4 + 32)             // ~112.6 KB

// ============================================================================
// PTX helpers
// ============================================================================
__device__ __forceinline__ uint32_t smem_to_u32(const void* p) {
    uint32_t a;
    asm("{ .reg .u64 t; cvta.to.shared.u64 t, %1; cvt.u32.u64 %0, t; }"
        : "=r"(a) : "l"(p));
    return a;
}

__device__ __forceinline__ void cp_async16(uint32_t s, const void* g) {
    asm volatile("cp.async.cg.shared.global [%0], [%1], 16;"
                 :: "r"(s), "l"(g) : "memory");
}
#define CP_COMMIT() asm volatile("cp.async.commit_group;" ::: "memory")
#define CP_WAIT(n)  asm volatile("cp.async.wait_group %0;" :: "n"(n) : "memory")

__device__ __forceinline__ void ldm_x4(uint32_t& r0, uint32_t& r1, uint32_t& r2,
                                       uint32_t& r3, uint32_t addr) {
    asm volatile("ldmatrix.sync.aligned.m8n8.x4.shared.b16 {%0,%1,%2,%3}, [%4];"
                 : "=r"(r0), "=r"(r1), "=r"(r2), "=r"(r3) : "r"(addr));
}

__device__ __forceinline__ void imma16832(int* c, uint32_t a0, uint32_t a1,
                                          uint32_t a2, uint32_t a3,
                                          uint32_t b0, uint32_t b1) {
    asm volatile(
        "mma.sync.aligned.m16n8k32.row.col.s32.s8.s8.s32 "
        "{%0,%1,%2,%3}, {%4,%5,%6,%7}, {%8,%9}, {%0,%1,%2,%3};"
        : "+r"(c[0]), "+r"(c[1]), "+r"(c[2]), "+r"(c[3])
        : "r"(a0), "r"(a1), "r"(a2), "r"(a3), "r"(b0), "r"(b1));
}

// FMA-pipe exp2: round-to-nearest range reduction + degree-4 Taylor on
// f in [-0.5, 0.5] (max rel err ~4e-5), exponent applied via integer add.
// Valid for x in [-126, 126]; our args are in [-60, -1].
__device__ __forceinline__ float exp2_poly(float x) {
    float r = rintf(x);
    float f = x - r;
    int e = (int)r;
    float y = 0.0096181f;
    y = fmaf(y, f, 0.0555041f);
    y = fmaf(y, f, 0.2402265f);
    y = fmaf(y, f, 0.6931472f);
    y = fmaf(y, f, 1.0f);
    return __int_as_float(__float_as_int(y) + (e << 23));
}

__global__ void reset_ctr_kernel(unsigned int v) { g_ctr = v; }

// ============================================================================
// Kernel 1a: quantize A + compute pos (reads both a and b rows once)
// ============================================================================
__global__ void __launch_bounds__(128) quantize_a_pos_kernel(const float* __restrict__ a,
                                                             const float* __restrict__ b) {
    int row = blockIdx.x;
    int t = threadIdx.x;
    const float4* a4 = (const float4*)a + (size_t)row * (DIM / 4);
    const float4* b4 = (const float4*)b + (size_t)row * (DIM / 4);
    float4 v0 = a4[t], v1 = a4[t + 128];
    float4 y0 = b4[t], y1 = b4[t + 128];
    float ss = v0.x * v0.x + v0.y * v0.y + v0.z * v0.z + v0.w * v0.w
             + v1.x * v1.x + v1.y * v1.y + v1.z * v1.z + v1.w * v1.w;
    float ma = fmaxf(fmaxf(fmaxf(fabsf(v0.x), fabsf(v0.y)), fmaxf(fabsf(v0.z), fabsf(v0.w))),
                     fmaxf(fmaxf(fabsf(v1.x), fabsf(v1.y)), fmaxf(fabsf(v1.z), fabsf(v1.w))));
    float dt = v0.x * y0.x + v0.y * y0.y + v0.z * y0.z + v0.w * y0.w
             + v1.x * y1.x + v1.y * y1.y + v1.z * y1.z + v1.w * y1.w;
    float nb = y0.x * y0.x + y0.y * y0.y + y0.z * y0.z + y0.w * y0.w
             + y1.x * y1.x + y1.y * y1.y + y1.z * y1.z + y1.w * y1.w;
    #pragma unroll
    for (int o = 16; o; o >>= 1) {
        ss += __shfl_xor_sync(0xffffffffu, ss, o);
        ma = fmaxf(ma, __shfl_xor_sync(0xffffffffu, ma, o));
        dt += __shfl_xor_sync(0xffffffffu, dt, o);
        nb += __shfl_xor_sync(0xffffffffu, nb, o);
    }
    __shared__ float wss[4], wma[4], wdt[4], wnb[4];
    if ((t & 31) == 0) { wss[t >> 5] = ss; wma[t >> 5] = ma; wdt[t >> 5] = dt; wnb[t >> 5] = nb; }
    __syncthreads();
    float inv = rsqrtf(wss[0] + wss[1] + wss[2] + wss[3]);
    float maxraw = fmaxf(fmaxf(wma[0], wma[1]), fmaxf(wma[2], wma[3]));
    float qs = 127.0f / maxraw;
    if (t == 0) {
        g_saL[row] = LOSS_SCALE * LOG2E * maxraw * inv * (1.0f / 127.0f);
        float dot = wdt[0] + wdt[1] + wdt[2] + wdt[3];
        float ib = rsqrtf(wnb[0] + wnb[1] + wnb[2] + wnb[3]);
        g_pos[row] = LOSS_SCALE * dot * inv * ib;
    }
    uint32_t p0 = ((uint32_t)(uint8_t)(int8_t)__float2int_rn(v0.x * qs))
                | ((uint32_t)(uint8_t)(int8_t)__float2int_rn(v0.y * qs) << 8)
                | ((uint32_t)(uint8_t)(int8_t)__float2int_rn(v0.z * qs) << 16)
                | ((uint32_t)(uint8_t)(int8_t)__float2int_rn(v0.w * qs) << 24);
    uint32_t p1 = ((uint32_t)(uint8_t)(int8_t)__float2int_rn(v1.x * qs))
                | ((uint32_t)(uint8_t)(int8_t)__float2int_rn(v1.y * qs) << 8)
                | ((uint32_t)(uint8_t)(int8_t)__float2int_rn(v1.z * qs) << 16)
                | ((uint32_t)(uint8_t)(int8_t)__float2int_rn(v1.w * qs) << 24);
    uint32_t* drow = (uint32_t*)(g_a_q + (size_t)row * DIM);
    drow[t] = p0;
    drow[128 + t] = p1;
}

// ============================================================================
// Kernel 1b: quantize B
// ============================================================================
__global__ void __launch_bounds__(128) quantize_b_kernel(const float* __restrict__ src) {
    int row = blockIdx.x;
    int t = threadIdx.x;
    const float4* s4 = (const float4*)src + (size_t)row * (DIM / 4);
    float4 v0 = s4[t];
    float4 v1 = s4[t + 128];
    float ss = v0.x * v0.x + v0.y * v0.y + v0.z * v0.z + v0.w * v0.w
             + v1.x * v1.x + v1.y * v1.y + v1.z * v1.z + v1.w * v1.w;
    float ma = fmaxf(fmaxf(fmaxf(fabsf(v0.x), fabsf(v0.y)), fmaxf(fabsf(v0.z), fabsf(v0.w))),
                     fmaxf(fmaxf(fabsf(v1.x), fabsf(v1.y)), fmaxf(fabsf(v1.z), fabsf(v1.w))));
    #pragma unroll
    for (int o = 16; o; o >>= 1) {
        ss += __shfl_xor_sync(0xffffffffu, ss, o);
        ma = fmaxf(ma, __shfl_xor_sync(0xffffffffu, ma, o));
    }
    __shared__ float wss[4], wma[4];
    if ((t & 31) == 0) { wss[t >> 5] = ss; wma[t >> 5] = ma; }
    __syncthreads();
    float inv = rsqrtf(wss[0] + wss[1] + wss[2] + wss[3]);
    float maxraw = fmaxf(fmaxf(wma[0], wma[1]), fmaxf(wma[2], wma[3]));
    float qs = 127.0f / maxraw;
    if (t == 0) g_sb[row] = maxraw * inv * (1.0f / 127.0f);
    uint32_t p0 = ((uint32_t)(uint8_t)(int8_t)__float2int_rn(v0.x * qs))
                | ((uint32_t)(uint8_t)(int8_t)__float2int_rn(v0.y * qs) << 8)
                | ((uint32_t)(uint8_t)(int8_t)__float2int_rn(v0.z * qs) << 16)
                | ((uint32_t)(uint8_t)(int8_t)__float2int_rn(v0.w * qs) << 24);
    uint32_t p1 = ((uint32_t)(uint8_t)(int8_t)__float2int_rn(v1.x * qs))
                | ((uint32_t)(uint8_t)(int8_t)__float2int_rn(v1.y * qs) << 8)
                | ((uint32_t)(uint8_t)(int8_t)__float2int_rn(v1.z * qs) << 16)
                | ((uint32_t)(uint8_t)(int8_t)__float2int_rn(v1.w * qs) << 24);
    uint32_t* drow = (uint32_t*)(g_b_q + (size_t)row * DIM);
    drow[t] = p0;
    drow[128 + t] = p1;
}

// ============================================================================
// Kernel 2: persistent fused int8 GEMM (IMMA k32) + fixed-max exp-sum partials
//   Item = (rb, chunk): 128x256 tile over full K. Work stolen via g_ctr.
//   Epilogue: s = sum exp2(logit*log2e - M2); half the exps on MUFU (exp2f),
//   half on the FMA pipe (exp2_poly) so the two streams overlap.
// ============================================================================
__global__ void __launch_bounds__(THREADS, 1) gemm_lse_kernel() {
    extern __shared__ char sm[];
    uint32_t sb = smem_to_u32(sm);

    int t = threadIdx.x;
    int lane = t & 31;
    int w = t >> 5;
    int wm = w >> 2;             // 0..1
    int wn = w & 3;              // 0..3

    float* red = (float*)(sm + SM_RED);          // [4][128]
    __shared__ int sm_next;

    int acc[4][8][4];
    #pragma unroll
    for (int mt = 0; mt < 4; mt++)
        #pragma unroll
        for (int nt = 0; nt < 8; nt++)
            #pragma unroll
            for (int j = 0; j < 4; j++) acc[mt][nt][j] = 0;

    // --- issue one stage of cp.asyncs for item `it`, k-chunk `kc`, buffer `buf`
    auto issue = [&](int it, int kc, int buf) {
        if (it < NITEMS) {
            int rb_ = it >> 6;
            int ch_ = it & 63;
            const char* ag = (const char*)g_a_q + (size_t)(rb_ * TM) * DIM;
            const char* bg = (const char*)g_b_q + (size_t)(ch_ * TN) * DIM;
            uint32_t sa = sb + SM_A(buf);
            uint32_t sbB = sb + SM_B(buf);
            size_t koff = (size_t)kc * TKS;
            #pragma unroll
            for (int i = 0; i < 4; i++) {
                int c = t + i * THREADS;
                int row = c >> 3, seg = c & 7;
                cp_async16(sa + row * PITCH_B + seg * 16,
                           ag + (size_t)row * DIM + koff + seg * 16);
            }
            #pragma unroll
            for (int i = 0; i < 8; i++) {
                int c = t + i * THREADS;
                int row = c >> 3, seg = c & 7;
                cp_async16(sbB + row * PITCH_B + seg * 16,
                           bg + (size_t)row * DIM + koff + seg * 16);
            }
        }
        CP_COMMIT();
    };

    int item = blockIdx.x;
    int ibuf = 0, cbuf = 0;
    issue(item, 0, ibuf); ibuf ^= 1;

    while (item < NITEMS) {
        int rb = item >> 6;
        int chunk = item & 63;

        // per-thread A row dequant scales (include 20*log2e)
        float sav[4][2];
        #pragma unroll
        for (int mt = 0; mt < 4; mt++)
            #pragma unroll
            for (int h = 0; h < 2; h++)
                sav[mt][h] = g_saL[rb * TM + wm * 64 + mt * 16 + h * 8 + (lane >> 2)];

        for (int s = 0; s < KSTAGES; s++) {
            CP_WAIT(0);
            __syncthreads();
            if (s == 0 && t == 0) sm_next = (int)atomicAdd(&g_ctr, 1u);
            if (s < KSTAGES - 1) issue(item, s + 1, ibuf);
            else issue(sm_next, 0, ibuf);   // sm_next visible: written s0, synced s1
            ibuf ^= 1;

            // A frags: 16 rows per mt; lanes 0-15: rows, lanes 16-31: +16B k-half
            uint32_t saA = sb + SM_A(cbuf)
                         + (uint32_t)(wm * 64 + (lane & 15)) * PITCH_B
                         + ((lane >> 4) * 16);
            // B frags: nt-pair per ldm_x4 (16 n-rows)
            uint32_t sbF = sb + SM_B(cbuf)
                         + (uint32_t)(wn * 64 + ((lane >> 4) & 1) * 8 + (lane & 7)) * PITCH_B
                         + (((lane >> 3) & 1) * 16);
            cbuf ^= 1;

            #pragma unroll
            for (int kk = 0; kk < 4; kk++) {            // 4 x k32 per 128B stage
                uint32_t a0[4], a1[4], a2[4], a3[4];
                uint32_t b0[8], b1[8];
                #pragma unroll
                for (int mt = 0; mt < 4; mt++)
                    ldm_x4(a0[mt], a1[mt], a2[mt], a3[mt],
                           saA + mt * 16 * PITCH_B + kk * 32);
                #pragma unroll
                for (int p = 0; p < 4; p++)
                    ldm_x4(b0[2 * p], b1[2 * p], b0[2 * p + 1], b1[2 * p + 1],
                           sbF + p * 16 * PITCH_B + kk * 32);
                #pragma unroll
                for (int mt = 0; mt < 4; mt++)
                    #pragma unroll
                    for (int nt = 0; nt < 8; nt++)
                        imma16832(acc[mt][nt], a0[mt], a1[mt], a2[mt], a3[mt],
                                  b0[nt], b1[nt]);
            }

            if (s == KSTAGES - 1) {
                // ---- fixed-max exp-sum epilogue for this item's 256 cols ----
                const float* sbp = g_sb + chunk * TN + wn * 64 + (lane & 3) * 2;
                float sbv[8][2];
                #pragma unroll
                for (int nt = 0; nt < 8; nt++) {
                    sbv[nt][0] = sbp[nt * 8];
                    sbv[nt][1] = sbp[nt * 8 + 1];
                }
                #pragma unroll
                for (int mt = 0; mt < 4; mt++) {
                    #pragma unroll
                    for (int h = 0; h < 2; h++) {
                        float rs = sav[mt][h];
                        float s0 = 0.f, s1 = 0.f;
                        #pragma unroll
                        for (int nt = 0; nt < 8; nt++) {
                            float f0 = (float)acc[mt][nt][2 * h + 0] * rs;
                            float f1 = (float)acc[mt][nt][2 * h + 1] * rs;
                            // j=0 via MUFU EX2, j=1 via FMA-pipe poly: pipe overlap
                            s0 += exp2f(fmaf(f0, sbv[nt][0], -M2));
                            s1 += exp2_poly(fmaf(f1, sbv[nt][1], -M2));
                            acc[mt][nt][2 * h + 0] = 0;
                            acc[mt][nt][2 * h + 1] = 0;
                        }
                        float ssum = s0 + s1;
                        // quad reduce (lanes xor 1,2 share the same output row)
                        ssum += __shfl_xor_sync(0xffffffffu, ssum, 1);
                        ssum += __shfl_xor_sync(0xffffffffu, ssum, 2);
                        if ((lane & 3) == 0) {
                            int row = wm * 64 + mt * 16 + h * 8 + (lane >> 2);
                            red[wn * 128 + row] = ssum;
                        }
                    }
                }
                __syncthreads();
                if (t < 128) {
                    float S = (red[t] + red[128 + t]) + (red[256 + t] + red[384 + t]);
                    g_ps[chunk * BA + rb * TM + t] = S;
                }
                // red[] not touched again until next item's epilogue (8 stages away)
            }
        }
        item = sm_next;
    }
    CP_WAIT(0);   // drain dangling empty commits
}

// ============================================================================
// Kernel 3/4: deterministic combine + mean.  lse_row = ln(S_total) + M_FIX
// ============================================================================
__global__ void __launch_bounds__(128) combine_kernel() {
    int row = blockIdx.x * 128 + threadIdx.x;
    float S = 0.f;
    #pragma unroll 8
    for (int c = 0; c < NCHUNK; c++)
        S += g_ps[c * BA + row];
    float li = logf(S) + M_FIX - g_pos[row];
    #pragma unroll
    for (int o = 16; o; o >>= 1) li += __shfl_xor_sync(0xffffffffu, li, o);
    __shared__ float ws[4];
    if ((threadIdx.x & 31) == 0) ws[threadIdx.x >> 5] = li;
    __syncthreads();
    if (threadIdx.x == 0) g_part[blockIdx.x] = ws[0] + ws[1] + ws[2] + ws[3];
}

__global__ void __launch_bounds__(64) final_kernel(float* __restrict__ out) {
    float v = g_part[threadIdx.x];
    #pragma unroll
    for (int o = 16; o; o >>= 1) v += __shfl_xor_sync(0xffffffffu, v, o);
    __shared__ float ws[2];
    if ((threadIdx.x & 31) == 0) ws[threadIdx.x >> 5] = v;
    __syncthreads();
    if (threadIdx.x == 0) out[0] = (ws[0] + ws[1]) * (1.0f / (float)BA);
}

// ============================================================================
// Launch
// ============================================================================
extern "C" void kernel_launch(void* const* d_in, const int* in_sizes, int n_in,
                              void* d_out, int out_size) {
    (void)in_sizes; (void)n_in; (void)out_size;
    const float* a = (const float*)d_in[0];
    const float* b = (const float*)d_in[1];
    float* out = (float*)d_out;

    int nsm = 0;
    cudaDeviceGetAttribute(&nsm, cudaDevAttrMultiProcessorCount, 0);
    if (nsm <= 0) nsm = 148;

    cudaFuncSetAttribute(gemm_lse_kernel,
                         cudaFuncAttributeMaxDynamicSharedMemorySize, SMEM_TOTAL);

    quantize_a_pos_kernel<<<BA, 128>>>(a, b);
    quantize_b_kernel<<<BB, 128>>>(b);
    reset_ctr_kernel<<<1, 1>>>((unsigned int)nsm);
    gemm_lse_kernel<<<nsm, THREADS, SMEM_TOTAL>>>();
    combine_kernel<<<ROWBLOCKS, 128>>>();
    final_kernel<<<1, 64>>>(out);
}